// round 9
// baseline (speedup 1.0000x reference)
#include <cuda_runtime.h>
#include <cuda_fp16.h>

// ===== static scratch (allocation-free rule: __device__ globals) =====
#define N_MAX 100352
#define E_MAX 1700032

__device__ int   g_cnt[N_MAX];
__device__ int   g_fill[N_MAX];
__device__ int   g_off[N_MAX + 1];
__device__ int   g_bsum[1024];
__device__ float g_dinv[N_MAX];
__device__ int   g_src[E_MAX];       // CSR src indices (weightless)

__device__ float g_a1[N_MAX];        // P·1
__device__ float g_at[N_MAX];        // dinv * a1
__device__ float g_a2[N_MAX];        // P²·1
__device__ float g_U[96 * 64];       // [W1@W3_top ; W2@W3_bot]
__device__ float g_c4[64];           // ([b1|b2]@W3)@W4
__device__ float g_e4[64];           // b3@W4
__device__ float g_f4[64];           // b4

__device__ __align__(16) __half g_T0[(size_t)N_MAX * 64];  // V, then Dinv·V (in place)
__device__ __align__(16) __half g_T1[(size_t)N_MAX * 64];
__device__ __align__(16) __half g_T2[(size_t)N_MAX * 64];
__device__ float                g_Y3[(size_t)N_MAX * 64];  // P³V

// ===== packed fp32x2 helpers (sm_103a) =====
__device__ __forceinline__ unsigned long long ffma2(unsigned long long a,
                                                    unsigned long long b,
                                                    unsigned long long c) {
    unsigned long long d;
    asm("fma.rn.f32x2 %0, %1, %2, %3;" : "=l"(d) : "l"(a), "l"(b), "l"(c));
    return d;
}
__device__ __forceinline__ unsigned long long pack2(float x) {
    unsigned long long d;
    asm("mov.b64 %0, {%1, %1};" : "=l"(d) : "r"(__float_as_uint(x)));
    return d;
}
__device__ __forceinline__ float2 unpack2(unsigned long long v) {
    unsigned int lo, hi;
    asm("mov.b64 {%0, %1}, %2;" : "=r"(lo), "=r"(hi) : "l"(v));
    return make_float2(__uint_as_float(lo), __uint_as_float(hi));
}

// ============================ graph construction ============================

__global__ void k_hist(const int* __restrict__ col, int E) {
    int e = blockIdx.x * blockDim.x + threadIdx.x;
    if (e < E) atomicAdd(&g_cnt[col[e]], 1);
}

__global__ void __launch_bounds__(1024) k_scan_local(int n) {
    __shared__ int s[1024];
    int tid = threadIdx.x;
    int i = blockIdx.x * 1024 + tid;
    int v = (i < n) ? g_cnt[i] : 0;
    s[tid] = v;
    __syncthreads();
    for (int d = 1; d < 1024; d <<= 1) {
        int t = (tid >= d) ? s[tid - d] : 0;
        __syncthreads();
        s[tid] += t;
        __syncthreads();
    }
    if (i < n) g_off[i] = s[tid] - v;
    if (tid == 1023) g_bsum[blockIdx.x] = s[1023];
}

__global__ void __launch_bounds__(1024) k_scan_bsum(int nb) {
    __shared__ int s[1024];
    int tid = threadIdx.x;
    int v = (tid < nb) ? g_bsum[tid] : 0;
    s[tid] = v;
    __syncthreads();
    for (int d = 1; d < 1024; d <<= 1) {
        int t = (tid >= d) ? s[tid - d] : 0;
        __syncthreads();
        s[tid] += t;
        __syncthreads();
    }
    if (tid < nb) g_bsum[tid] = s[tid] - v;
}

// ============================ weight precompute (parallel) ============================
__global__ void __launch_bounds__(256) k_wprep2(
        const float* __restrict__ W1, const float* __restrict__ W2,
        const float* __restrict__ W3, const float* __restrict__ W4,
        const float* __restrict__ b1, const float* __restrict__ b2,
        const float* __restrict__ b3, const float* __restrict__ b4) {
    int tid = threadIdx.x;
    int b = blockIdx.x;
    if (b < 24) {
        __shared__ float sB[64 * 64];
        __shared__ float sA[4 * 64];
        int k0 = b * 4;
        int half = (k0 >= 64);
        const float* Wsrc = W3 + (size_t)half * 64 * 64;
        for (int i = tid; i < 64 * 64; i += 256) sB[i] = Wsrc[i];
        const float* Arow = half ? (W2 + (size_t)(k0 - 64) * 64) : (W1 + (size_t)k0 * 64);
        sA[tid] = Arow[tid];
        __syncthreads();
        int k = tid >> 6, j = tid & 63;
        float s = 0.f;
#pragma unroll
        for (int m = 0; m < 64; m++) s += sA[k * 64 + m] * sB[m * 64 + j];
        g_U[(k0 + k) * 64 + j] = s;
    } else {
        __shared__ float c3[64];
        int j = tid & 63;
        if (tid < 64) {
            float s = 0.f;
            for (int m = 0; m < 128; m++)
                s += ((m < 64) ? b1[m] : b2[m - 64]) * W3[m * 64 + j];
            c3[j] = s;
        }
        __syncthreads();
        if (tid < 64) {
            float s = 0.f, t = 0.f;
            for (int m = 0; m < 64; m++) {
                s += c3[m] * W4[m * 64 + j];
                t += b3[m] * W4[m * 64 + j];
            }
            g_c4[j] = s; g_e4[j] = t; g_f4[j] = b4[j];
        }
    }
}

__global__ void k_scan_add(int n, int E) {
    int i = blockIdx.x * blockDim.x + threadIdx.x;
    if (i < n) {
        int o = g_off[i] + g_bsum[i >> 10];
        g_off[i]  = o;
        g_fill[i] = o;
        g_dinv[i] = rsqrtf((float)(g_cnt[i] + 1));
    }
    if (i == n) g_off[n] = E;
}

// fill CSR src (single int atomic per edge)
__global__ void k_fill(const int* __restrict__ row, const int* __restrict__ col, int E) {
    int e = blockIdx.x * blockDim.x + threadIdx.x;
    if (e < E) {
        int r = row[e], c = col[e];
        int pos = atomicAdd(&g_fill[c], 1);
        g_src[pos] = r;
    }
}

// ============================ gemm0v: V = [L|C]@U (fp16, UNSCALED) ============================
__global__ void __launch_bounds__(256) k_gemm0v(const float* __restrict__ latent,
                                                const float* __restrict__ cond, int n) {
    __shared__ __align__(16) float sW[96 * 64];
    for (int i = threadIdx.x; i < 96 * 64; i += blockDim.x) sW[i] = g_U[i];
    __syncthreads();
    int node = blockIdx.x * blockDim.x + threadIdx.x;
    if (node >= n) return;

    unsigned long long acc[32];
#pragma unroll
    for (int j = 0; j < 32; j++) acc[j] = 0ull;

    const float* pL = latent + (size_t)node * 64;
    const float* pC = cond   + (size_t)node * 32;
#pragma unroll 2
    for (int k = 0; k < 96; k += 4) {
        float4 av = (k < 64) ? *reinterpret_cast<const float4*>(pL + k)
                             : *reinterpret_cast<const float4*>(pC + (k - 64));
        unsigned long long p0 = pack2(av.x), p1 = pack2(av.y);
        unsigned long long p2 = pack2(av.z), p3 = pack2(av.w);
        const ulonglong2* w0 = reinterpret_cast<const ulonglong2*>(sW + (k + 0) * 64);
        const ulonglong2* w1 = reinterpret_cast<const ulonglong2*>(sW + (k + 1) * 64);
        const ulonglong2* w2 = reinterpret_cast<const ulonglong2*>(sW + (k + 2) * 64);
        const ulonglong2* w3 = reinterpret_cast<const ulonglong2*>(sW + (k + 3) * 64);
#pragma unroll
        for (int j = 0; j < 16; j++) {
            ulonglong2 q;
            q = w0[j]; acc[2*j] = ffma2(p0, q.x, acc[2*j]); acc[2*j+1] = ffma2(p0, q.y, acc[2*j+1]);
            q = w1[j]; acc[2*j] = ffma2(p1, q.x, acc[2*j]); acc[2*j+1] = ffma2(p1, q.y, acc[2*j+1]);
            q = w2[j]; acc[2*j] = ffma2(p2, q.x, acc[2*j]); acc[2*j+1] = ffma2(p2, q.y, acc[2*j+1]);
            q = w3[j]; acc[2*j] = ffma2(p3, q.x, acc[2*j]); acc[2*j+1] = ffma2(p3, q.y, acc[2*j+1]);
        }
    }

    __half* yp = g_T0 + (size_t)node * 64;
#pragma unroll
    for (int j = 0; j < 8; j++) {
        float2 f0 = unpack2(acc[4*j+0]);
        float2 f1 = unpack2(acc[4*j+1]);
        float2 f2 = unpack2(acc[4*j+2]);
        float2 f3 = unpack2(acc[4*j+3]);
        __half2 h0 = __floats2half2_rn(f0.x, f0.y);
        __half2 h1 = __floats2half2_rn(f1.x, f1.y);
        __half2 h2 = __floats2half2_rn(f2.x, f2.y);
        __half2 h3 = __floats2half2_rn(f3.x, f3.y);
        uint4 u = make_uint4(*reinterpret_cast<unsigned*>(&h0), *reinterpret_cast<unsigned*>(&h1),
                             *reinterpret_cast<unsigned*>(&h2), *reinterpret_cast<unsigned*>(&h3));
        *reinterpret_cast<uint4*>(yp + 8 * j) = u;
    }
}

// ============================ scale: T0 *= dinv (in place) ============================
__global__ void k_scale(int n) {
    int idx = blockIdx.x * blockDim.x + threadIdx.x;
    if (idx >= n * 8) return;
    int node = idx >> 3;
    int c = (idx & 7) * 8;
    float dn = g_dinv[node];
    __half* p = g_T0 + (size_t)node * 64 + c;
    uint4 u = *reinterpret_cast<uint4*>(p);
    __half2* h = reinterpret_cast<__half2*>(&u);
#pragma unroll
    for (int q = 0; q < 4; q++) {
        float2 f = __half22float2(h[q]);
        h[q] = __floats2half2_rn(f.x * dn, f.y * dn);
    }
    *reinterpret_cast<uint4*>(p) = u;
}

// a1 = P·1 via CSR gather of dinv; at = dinv·a1   (side stream)
__global__ void k_a1(int n) {
    int wid  = (blockIdx.x * blockDim.x + threadIdx.x) >> 5;
    int lane = threadIdx.x & 31;
    if (wid >= n) return;
    int beg = g_off[wid], end = g_off[wid + 1];
    float acc = 0.f;
    for (int e = beg + lane; e < end; e += 32) acc += g_dinv[g_src[e]];
    for (int d = 16; d; d >>= 1) acc += __shfl_down_sync(0xffffffffu, acc, d);
    if (lane == 0) {
        float dn = g_dinv[wid];
        float a1 = dn * (acc + dn);
        g_a1[wid] = a1;
        g_at[wid] = dn * a1;
    }
}

// a2 = P·a1   (side stream)
__global__ void k_a2(int n) {
    int wid  = (blockIdx.x * blockDim.x + threadIdx.x) >> 5;
    int lane = threadIdx.x & 31;
    if (wid >= n) return;
    int beg = g_off[wid], end = g_off[wid + 1];
    float acc = 0.f;
    for (int e = beg + lane; e < end; e += 32) acc += g_at[g_src[e]];
    for (int d = 16; d; d >>= 1) acc += __shfl_down_sync(0xffffffffu, acc, d);
    if (lane == 0) g_a2[wid] = g_dinv[wid] * (acc + g_at[wid]);
}

// ============================ weightless aggregation ============================
template <int MODE>
__global__ void __launch_bounds__(256) k_aggp(const __half* __restrict__ X,
                                              void* __restrict__ Yv, int n) {
    int wid  = (blockIdx.x * blockDim.x + threadIdx.x) >> 5;
    int lane = threadIdx.x & 31;
    if (wid >= n) return;

    const int f0 = lane * 2;
    int e = g_off[wid];
    const int end = g_off[wid + 1];
    float a0 = 0.f, a1v = 0.f;

#define GATH(SRC) { __half2 h = *reinterpret_cast<const __half2*>(X + (size_t)(SRC) * 64 + f0); \
                    float2 f = __half22float2(h); a0 += f.x; a1v += f.y; }

    for (; e + 8 <= end; e += 8) {
        int s0 = g_src[e+0], s1 = g_src[e+1], s2 = g_src[e+2], s3 = g_src[e+3];
        int s4 = g_src[e+4], s5 = g_src[e+5], s6 = g_src[e+6], s7 = g_src[e+7];
        GATH(s0) GATH(s1) GATH(s2) GATH(s3) GATH(s4) GATH(s5) GATH(s6) GATH(s7)
    }
    for (; e < end; ++e) { int s = g_src[e]; GATH(s) }
    GATH(wid)  // self loop
#undef GATH

    float dn = g_dinv[wid];
    if (MODE == 0) {
        float s = dn * dn;
        __half2 h = __floats2half2_rn(a0 * s, a1v * s);
        *reinterpret_cast<__half2*>((__half*)Yv + (size_t)wid * 64 + f0) = h;
    } else {
        *reinterpret_cast<float2*>((float*)Yv + (size_t)wid * 64 + f0) =
            make_float2(a0 * dn, a1v * dn);
    }
}

// ============================ final GEMM ============================
__global__ void __launch_bounds__(256) k_gemm_final(const float* __restrict__ A,
                                                    const float* __restrict__ Wg,
                                                    float* __restrict__ Y, int n) {
    __shared__ __align__(16) float sW[64 * 64];
    __shared__ float sc[64], se[64], sf[64];
    for (int i = threadIdx.x; i < 64 * 64; i += blockDim.x) sW[i] = Wg[i];
    if (threadIdx.x < 64) {
        sc[threadIdx.x] = g_c4[threadIdx.x];
        se[threadIdx.x] = g_e4[threadIdx.x];
        sf[threadIdx.x] = g_f4[threadIdx.x];
    }
    __syncthreads();
    int node = blockIdx.x * blockDim.x + threadIdx.x;
    if (node >= n) return;

    unsigned long long acc[32];
#pragma unroll
    for (int j = 0; j < 32; j++) acc[j] = 0ull;

    const float* arow = A + (size_t)node * 64;
#pragma unroll 2
    for (int k = 0; k < 64; k += 4) {
        float4 av = *reinterpret_cast<const float4*>(arow + k);
        unsigned long long p0 = pack2(av.x), p1 = pack2(av.y);
        unsigned long long p2 = pack2(av.z), p3 = pack2(av.w);
        const ulonglong2* w0 = reinterpret_cast<const ulonglong2*>(sW + (k + 0) * 64);
        const ulonglong2* w1 = reinterpret_cast<const ulonglong2*>(sW + (k + 1) * 64);
        const ulonglong2* w2 = reinterpret_cast<const ulonglong2*>(sW + (k + 2) * 64);
        const ulonglong2* w3 = reinterpret_cast<const ulonglong2*>(sW + (k + 3) * 64);
#pragma unroll
        for (int j = 0; j < 16; j++) {
            ulonglong2 q;
            q = w0[j]; acc[2*j] = ffma2(p0, q.x, acc[2*j]); acc[2*j+1] = ffma2(p0, q.y, acc[2*j+1]);
            q = w1[j]; acc[2*j] = ffma2(p1, q.x, acc[2*j]); acc[2*j+1] = ffma2(p1, q.y, acc[2*j+1]);
            q = w2[j]; acc[2*j] = ffma2(p2, q.x, acc[2*j]); acc[2*j+1] = ffma2(p2, q.y, acc[2*j+1]);
            q = w3[j]; acc[2*j] = ffma2(p3, q.x, acc[2*j]); acc[2*j+1] = ffma2(p3, q.y, acc[2*j+1]);
        }
    }

    float av1 = g_a1[node], av2 = g_a2[node];
    float* yrow = Y + (size_t)node * 64;
#pragma unroll
    for (int j = 0; j < 16; j++) {
        float2 lo = unpack2(acc[2*j]);
        float2 hi = unpack2(acc[2*j+1]);
        int c0 = 4 * j;
        float4 o;
        o.x = lo.x + av2 * sc[c0+0] + av1 * se[c0+0] + sf[c0+0];
        o.y = lo.y + av2 * sc[c0+1] + av1 * se[c0+1] + sf[c0+1];
        o.z = hi.x + av2 * sc[c0+2] + av1 * se[c0+2] + sf[c0+2];
        o.w = hi.y + av2 * sc[c0+3] + av1 * se[c0+3] + sf[c0+3];
        *reinterpret_cast<float4*>(yrow + c0) = o;
    }
}

// ============================ launch ============================

extern "C" void kernel_launch(void* const* d_in, const int* in_sizes, int n_in,
                              void* d_out, int out_size) {
    const float* latent = (const float*)d_in[0];
    const float* cond   = (const float*)d_in[1];
    const int*   edge   = (const int*)  d_in[2];
    const float* W1 = (const float*)d_in[3];
    const float* b1 = (const float*)d_in[4];
    const float* W2 = (const float*)d_in[5];
    const float* b2 = (const float*)d_in[6];
    const float* W3 = (const float*)d_in[7];
    const float* b3 = (const float*)d_in[8];
    const float* W4 = (const float*)d_in[9];
    const float* b4 = (const float*)d_in[10];

    const int n = in_sizes[0] / 64;      // 100000
    const int E = in_sizes[2] / 2;       // 1600000
    const int* row = edge;
    const int* col = edge + E;

    static int* pCnt = nullptr;
    static __half *pT0 = nullptr, *pT1 = nullptr, *pT2 = nullptr;
    static float *pY3 = nullptr;
    static cudaStream_t sB = nullptr;
    static cudaEvent_t ev0 = nullptr, evAdd = nullptr, evFill = nullptr,
                       evScale = nullptr, evA2 = nullptr;
    if (!pCnt) {
        cudaGetSymbolAddress((void**)&pCnt, g_cnt);
        cudaGetSymbolAddress((void**)&pT0,  g_T0);
        cudaGetSymbolAddress((void**)&pT1,  g_T1);
        cudaGetSymbolAddress((void**)&pT2,  g_T2);
        cudaGetSymbolAddress((void**)&pY3,  g_Y3);
        cudaStreamCreateWithFlags(&sB, cudaStreamNonBlocking);
        cudaEventCreateWithFlags(&ev0,     cudaEventDisableTiming);
        cudaEventCreateWithFlags(&evAdd,   cudaEventDisableTiming);
        cudaEventCreateWithFlags(&evFill,  cudaEventDisableTiming);
        cudaEventCreateWithFlags(&evScale, cudaEventDisableTiming);
        cudaEventCreateWithFlags(&evA2,    cudaEventDisableTiming);
    }

    const int TB  = 256;
    const int gN  = (n + TB - 1) / TB;
    const int gE  = (E + TB - 1) / TB;
    const int nbS = (n + 1023) / 1024;
    const int gN1 = (n + 1 + TB - 1) / TB;
    const int gW  = (n + 7) / 8;           // warp per node, 8 warps/block
    const int gS  = (n * 8 + TB - 1) / TB; // scale kernel

    // ---- fork: side stream B handles the weight path ----
    cudaEventRecord(ev0, 0);
    cudaStreamWaitEvent(sB, ev0, 0);
    k_wprep2<<<25, 256, 0, sB>>>(W1, W2, W3, W4, b1, b2, b3, b4);
    k_gemm0v<<<gN, TB, 0, sB>>>(latent, cond, n);   // V = [L|C]@U (unscaled)

    // ---- main stream: edge/build chain ----
    cudaMemsetAsync(pCnt, 0, (size_t)n * sizeof(int));
    k_hist<<<gE, TB>>>(col, E);
    k_scan_local<<<nbS, 1024>>>(n);
    k_scan_bsum<<<1, 1024>>>(nbS);
    k_scan_add<<<gN1, TB>>>(n, E);
    cudaEventRecord(evAdd, 0);
    k_fill<<<gE, TB>>>(row, col, E);
    cudaEventRecord(evFill, 0);

    // ---- side stream: scale T0 by dinv (needs scan_add + gemm0v), concurrent with fill ----
    cudaStreamWaitEvent(sB, evAdd, 0);
    k_scale<<<gS, TB, 0, sB>>>(n);
    cudaEventRecord(evScale, sB);

    // ---- side stream: a1, a2 gathers (need fill), concurrent with agg passes ----
    cudaStreamWaitEvent(sB, evFill, 0);
    k_a1<<<gW, TB, 0, sB>>>(n);
    k_a2<<<gW, TB, 0, sB>>>(n);
    cudaEventRecord(evA2, sB);

    // ---- main stream: three aggregation passes (agg1 waits for scale) ----
    cudaStreamWaitEvent(0, evScale, 0);
    k_aggp<0><<<gW, TB>>>(pT0, pT1, n);
    k_aggp<0><<<gW, TB>>>(pT1, pT2, n);
    k_aggp<1><<<gW, TB>>>(pT2, pY3, n);

    // ---- out = Y3@W4 + a2·c4 + a1·e4 + f4 ----
    cudaStreamWaitEvent(0, evA2, 0);
    k_gemm_final<<<gN, TB>>>(pY3, W4, (float*)d_out, n);
}

// round 10
// speedup vs baseline: 1.0178x; 1.0178x over previous
#include <cuda_runtime.h>
#include <cuda_fp16.h>

// ===== static scratch (allocation-free rule: __device__ globals) =====
#define N_MAX 100352
#define E_MAX 1700032

__device__ int   g_cnt[N_MAX];       // zero at load; self-cleaned by k_a2 each run
__device__ int   g_fill[N_MAX];
__device__ int   g_off[N_MAX + 1];
__device__ int   g_bsum[1024];
__device__ float g_dinv[N_MAX];
__device__ float g_a1f[N_MAX];       // atomic accum of sum dinv[src]; self-cleaned by k_a2
__device__ int   g_src[E_MAX];       // CSR src indices (weightless)

__device__ float g_a1[N_MAX];        // P·1
__device__ float g_at[N_MAX];        // dinv * a1
__device__ float g_a2[N_MAX];        // P²·1
__device__ float g_U[96 * 64];       // [W1@W3_top ; W2@W3_bot]
__device__ float g_c4[64];           // ([b1|b2]@W3)@W4
__device__ float g_e4[64];           // b3@W4
__device__ float g_f4[64];           // b4

__device__ __align__(16) __half g_T0[(size_t)N_MAX * 64];  // V, then Dinv·V (in place)
__device__ __align__(16) __half g_T1[(size_t)N_MAX * 64];
__device__ __align__(16) __half g_T2[(size_t)N_MAX * 64];
__device__ float                g_Y3[(size_t)N_MAX * 64];  // P³V

// ===== packed fp32x2 helpers (sm_103a) =====
__device__ __forceinline__ unsigned long long ffma2(unsigned long long a,
                                                    unsigned long long b,
                                                    unsigned long long c) {
    unsigned long long d;
    asm("fma.rn.f32x2 %0, %1, %2, %3;" : "=l"(d) : "l"(a), "l"(b), "l"(c));
    return d;
}
__device__ __forceinline__ unsigned long long pack2(float x) {
    unsigned long long d;
    asm("mov.b64 %0, {%1, %1};" : "=l"(d) : "r"(__float_as_uint(x)));
    return d;
}
__device__ __forceinline__ float2 unpack2(unsigned long long v) {
    unsigned int lo, hi;
    asm("mov.b64 {%0, %1}, %2;" : "=r"(lo), "=r"(hi) : "l"(v));
    return make_float2(__uint_as_float(lo), __uint_as_float(hi));
}

// ============================ graph construction ============================

__global__ void k_hist(const int* __restrict__ col, int E) {
    int e = blockIdx.x * blockDim.x + threadIdx.x;
    if (e < E) atomicAdd(&g_cnt[col[e]], 1);
}

__global__ void __launch_bounds__(1024) k_scan_local(int n) {
    __shared__ int s[1024];
    int tid = threadIdx.x;
    int i = blockIdx.x * 1024 + tid;
    int v = (i < n) ? g_cnt[i] : 0;
    s[tid] = v;
    __syncthreads();
    for (int d = 1; d < 1024; d <<= 1) {
        int t = (tid >= d) ? s[tid - d] : 0;
        __syncthreads();
        s[tid] += t;
        __syncthreads();
    }
    if (i < n) g_off[i] = s[tid] - v;
    if (tid == 1023) g_bsum[blockIdx.x] = s[1023];
}

// merged: every block re-scans the <=128 per-block sums in smem, then finalizes.
__global__ void __launch_bounds__(256) k_scan_add(int n, int E, int nb) {
    __shared__ int sb[128];
    int tid = threadIdx.x;
    if (tid < 128) sb[tid] = (tid < nb) ? g_bsum[tid] : 0;
    __syncthreads();
    for (int d = 1; d < 128; d <<= 1) {
        int t = (tid >= d && tid < 128) ? sb[tid - d] : 0;
        __syncthreads();
        if (tid < 128) sb[tid] += t;   // inclusive scan
        __syncthreads();
    }
    int i = blockIdx.x * blockDim.x + tid;
    if (i < n) {
        int b = i >> 10;
        int pre = b ? sb[b - 1] : 0;
        int o = g_off[i] + pre;
        g_off[i]  = o;
        g_fill[i] = o;
        g_dinv[i] = rsqrtf((float)(g_cnt[i] + 1));
    }
    if (i == n) g_off[n] = E;
}

// fill CSR src; accumulate a1f[c] += dinv[r]
__global__ void k_fill(const int* __restrict__ row, const int* __restrict__ col, int E) {
    int e = blockIdx.x * blockDim.x + threadIdx.x;
    if (e < E) {
        int r = row[e], c = col[e];
        int pos = atomicAdd(&g_fill[c], 1);
        g_src[pos] = r;
        atomicAdd(&g_a1f[c], g_dinv[r]);
    }
}

// ============================ weight precompute (parallel, side stream) ============================
__global__ void __launch_bounds__(256) k_wprep2(
        const float* __restrict__ W1, const float* __restrict__ W2,
        const float* __restrict__ W3, const float* __restrict__ W4,
        const float* __restrict__ b1, const float* __restrict__ b2,
        const float* __restrict__ b3, const float* __restrict__ b4) {
    int tid = threadIdx.x;
    int b = blockIdx.x;
    if (b < 24) {
        __shared__ float sB[64 * 64];
        __shared__ float sA[4 * 64];
        int k0 = b * 4;
        int half = (k0 >= 64);
        const float* Wsrc = W3 + (size_t)half * 64 * 64;
        for (int i = tid; i < 64 * 64; i += 256) sB[i] = Wsrc[i];
        const float* Arow = half ? (W2 + (size_t)(k0 - 64) * 64) : (W1 + (size_t)k0 * 64);
        sA[tid] = Arow[tid];
        __syncthreads();
        int k = tid >> 6, j = tid & 63;
        float s = 0.f;
#pragma unroll
        for (int m = 0; m < 64; m++) s += sA[k * 64 + m] * sB[m * 64 + j];
        g_U[(k0 + k) * 64 + j] = s;
    } else {
        __shared__ float c3[64];
        int j = tid & 63;
        if (tid < 64) {
            float s = 0.f;
            for (int m = 0; m < 128; m++)
                s += ((m < 64) ? b1[m] : b2[m - 64]) * W3[m * 64 + j];
            c3[j] = s;
        }
        __syncthreads();
        if (tid < 64) {
            float s = 0.f, t = 0.f;
            for (int m = 0; m < 64; m++) {
                s += c3[m] * W4[m * 64 + j];
                t += b3[m] * W4[m * 64 + j];
            }
            g_c4[j] = s; g_e4[j] = t; g_f4[j] = b4[j];
        }
    }
}

// ============================ gemm0v: V = [L|C]@U (fp16, unscaled; side stream) ============================
__global__ void __launch_bounds__(256) k_gemm0v(const float* __restrict__ latent,
                                                const float* __restrict__ cond, int n) {
    __shared__ __align__(16) float sW[96 * 64];
    for (int i = threadIdx.x; i < 96 * 64; i += blockDim.x) sW[i] = g_U[i];
    __syncthreads();
    int node = blockIdx.x * blockDim.x + threadIdx.x;
    if (node >= n) return;

    unsigned long long acc[32];
#pragma unroll
    for (int j = 0; j < 32; j++) acc[j] = 0ull;

    const float* pL = latent + (size_t)node * 64;
    const float* pC = cond   + (size_t)node * 32;
#pragma unroll 2
    for (int k = 0; k < 96; k += 4) {
        float4 av = (k < 64) ? *reinterpret_cast<const float4*>(pL + k)
                             : *reinterpret_cast<const float4*>(pC + (k - 64));
        unsigned long long p0 = pack2(av.x), p1 = pack2(av.y);
        unsigned long long p2 = pack2(av.z), p3 = pack2(av.w);
        const ulonglong2* w0 = reinterpret_cast<const ulonglong2*>(sW + (k + 0) * 64);
        const ulonglong2* w1 = reinterpret_cast<const ulonglong2*>(sW + (k + 1) * 64);
        const ulonglong2* w2 = reinterpret_cast<const ulonglong2*>(sW + (k + 2) * 64);
        const ulonglong2* w3 = reinterpret_cast<const ulonglong2*>(sW + (k + 3) * 64);
#pragma unroll
        for (int j = 0; j < 16; j++) {
            ulonglong2 q;
            q = w0[j]; acc[2*j] = ffma2(p0, q.x, acc[2*j]); acc[2*j+1] = ffma2(p0, q.y, acc[2*j+1]);
            q = w1[j]; acc[2*j] = ffma2(p1, q.x, acc[2*j]); acc[2*j+1] = ffma2(p1, q.y, acc[2*j+1]);
            q = w2[j]; acc[2*j] = ffma2(p2, q.x, acc[2*j]); acc[2*j+1] = ffma2(p2, q.y, acc[2*j+1]);
            q = w3[j]; acc[2*j] = ffma2(p3, q.x, acc[2*j]); acc[2*j+1] = ffma2(p3, q.y, acc[2*j+1]);
        }
    }

    __half* yp = g_T0 + (size_t)node * 64;
#pragma unroll
    for (int j = 0; j < 8; j++) {
        float2 f0 = unpack2(acc[4*j+0]);
        float2 f1 = unpack2(acc[4*j+1]);
        float2 f2 = unpack2(acc[4*j+2]);
        float2 f3 = unpack2(acc[4*j+3]);
        __half2 h0 = __floats2half2_rn(f0.x, f0.y);
        __half2 h1 = __floats2half2_rn(f1.x, f1.y);
        __half2 h2 = __floats2half2_rn(f2.x, f2.y);
        __half2 h3 = __floats2half2_rn(f3.x, f3.y);
        uint4 u = make_uint4(*reinterpret_cast<unsigned*>(&h0), *reinterpret_cast<unsigned*>(&h1),
                             *reinterpret_cast<unsigned*>(&h2), *reinterpret_cast<unsigned*>(&h3));
        *reinterpret_cast<uint4*>(yp + 8 * j) = u;
    }
}

// ============================ scale: T0 *= dinv (in place; side stream, overlaps fill) ============================
__global__ void k_scale(int n) {
    int idx = blockIdx.x * blockDim.x + threadIdx.x;
    if (idx >= n * 8) return;
    int node = idx >> 3;
    int c = (idx & 7) * 8;
    float dn = g_dinv[node];
    __half* p = g_T0 + (size_t)node * 64 + c;
    uint4 u = *reinterpret_cast<uint4*>(p);
    __half2* h = reinterpret_cast<__half2*>(&u);
#pragma unroll
    for (int q = 0; q < 4; q++) {
        float2 f = __half22float2(h[q]);
        h[q] = __floats2half2_rn(f.x * dn, f.y * dn);
    }
    *reinterpret_cast<uint4*>(p) = u;
}

// a2 = P·a1 (side stream, overlaps agg2/agg3); also self-cleans cnt & a1f for next run
__global__ void k_a2(int n) {
    int wid  = (blockIdx.x * blockDim.x + threadIdx.x) >> 5;
    int lane = threadIdx.x & 31;
    if (wid >= n) return;
    int beg = g_off[wid], end = g_off[wid + 1];
    float acc = 0.f;
    for (int e = beg + lane; e < end; e += 32) acc += g_at[g_src[e]];
    for (int d = 16; d; d >>= 1) acc += __shfl_down_sync(0xffffffffu, acc, d);
    if (lane == 0) g_a2[wid] = g_dinv[wid] * (acc + g_at[wid]);
    if (lane == 1) g_cnt[wid] = 0;     // self-clean for next replay
    if (lane == 2) g_a1f[wid] = 0.f;
}

// ============================ weightless aggregation ============================
// G[c] = sum_{e->c} X[src_e] + X[c];  MODE 0: fp16 out (dinv²), MODE 1: fp32 out (dinv)
// FIRST: lane0 finalizes a1/at from a1f (pass 1 only).
template <int MODE, bool FIRST>
__global__ void __launch_bounds__(256) k_aggp(const __half* __restrict__ X,
                                              void* __restrict__ Yv, int n) {
    int wid  = (blockIdx.x * blockDim.x + threadIdx.x) >> 5;
    int lane = threadIdx.x & 31;
    if (wid >= n) return;

    const int f0 = lane * 2;
    int e = g_off[wid];
    const int end = g_off[wid + 1];
    float a0 = 0.f, a1v = 0.f;

#define GATH(SRC) { __half2 h = *reinterpret_cast<const __half2*>(X + (size_t)(SRC) * 64 + f0); \
                    float2 f = __half22float2(h); a0 += f.x; a1v += f.y; }

    for (; e + 8 <= end; e += 8) {
        int s0 = g_src[e+0], s1 = g_src[e+1], s2 = g_src[e+2], s3 = g_src[e+3];
        int s4 = g_src[e+4], s5 = g_src[e+5], s6 = g_src[e+6], s7 = g_src[e+7];
        GATH(s0) GATH(s1) GATH(s2) GATH(s3) GATH(s4) GATH(s5) GATH(s6) GATH(s7)
    }
    for (; e < end; ++e) { int s = g_src[e]; GATH(s) }
    GATH(wid)  // self loop
#undef GATH

    float dn = g_dinv[wid];
    if (FIRST && lane == 0) {
        float a1 = dn * (g_a1f[wid] + dn);
        g_a1[wid] = a1;
        g_at[wid] = dn * a1;
    }
    if (MODE == 0) {
        float s = dn * dn;
        __half2 h = __floats2half2_rn(a0 * s, a1v * s);
        *reinterpret_cast<__half2*>((__half*)Yv + (size_t)wid * 64 + f0) = h;
    } else {
        *reinterpret_cast<float2*>((float*)Yv + (size_t)wid * 64 + f0) =
            make_float2(a0 * dn, a1v * dn);
    }
}

// ============================ final GEMM ============================
__global__ void __launch_bounds__(256) k_gemm_final(const float* __restrict__ A,
                                                    const float* __restrict__ Wg,
                                                    float* __restrict__ Y, int n) {
    __shared__ __align__(16) float sW[64 * 64];
    __shared__ float sc[64], se[64], sf[64];
    for (int i = threadIdx.x; i < 64 * 64; i += blockDim.x) sW[i] = Wg[i];
    if (threadIdx.x < 64) {
        sc[threadIdx.x] = g_c4[threadIdx.x];
        se[threadIdx.x] = g_e4[threadIdx.x];
        sf[threadIdx.x] = g_f4[threadIdx.x];
    }
    __syncthreads();
    int node = blockIdx.x * blockDim.x + threadIdx.x;
    if (node >= n) return;

    unsigned long long acc[32];
#pragma unroll
    for (int j = 0; j < 32; j++) acc[j] = 0ull;

    const float* arow = A + (size_t)node * 64;
#pragma unroll 2
    for (int k = 0; k < 64; k += 4) {
        float4 av = *reinterpret_cast<const float4*>(arow + k);
        unsigned long long p0 = pack2(av.x), p1 = pack2(av.y);
        unsigned long long p2 = pack2(av.z), p3 = pack2(av.w);
        const ulonglong2* w0 = reinterpret_cast<const ulonglong2*>(sW + (k + 0) * 64);
        const ulonglong2* w1 = reinterpret_cast<const ulonglong2*>(sW + (k + 1) * 64);
        const ulonglong2* w2 = reinterpret_cast<const ulonglong2*>(sW + (k + 2) * 64);
        const ulonglong2* w3 = reinterpret_cast<const ulonglong2*>(sW + (k + 3) * 64);
#pragma unroll
        for (int j = 0; j < 16; j++) {
            ulonglong2 q;
            q = w0[j]; acc[2*j] = ffma2(p0, q.x, acc[2*j]); acc[2*j+1] = ffma2(p0, q.y, acc[2*j+1]);
            q = w1[j]; acc[2*j] = ffma2(p1, q.x, acc[2*j]); acc[2*j+1] = ffma2(p1, q.y, acc[2*j+1]);
            q = w2[j]; acc[2*j] = ffma2(p2, q.x, acc[2*j]); acc[2*j+1] = ffma2(p2, q.y, acc[2*j+1]);
            q = w3[j]; acc[2*j] = ffma2(p3, q.x, acc[2*j]); acc[2*j+1] = ffma2(p3, q.y, acc[2*j+1]);
        }
    }

    float av1 = g_a1[node], av2 = g_a2[node];
    float* yrow = Y + (size_t)node * 64;
#pragma unroll
    for (int j = 0; j < 16; j++) {
        float2 lo = unpack2(acc[2*j]);
        float2 hi = unpack2(acc[2*j+1]);
        int c0 = 4 * j;
        float4 o;
        o.x = lo.x + av2 * sc[c0+0] + av1 * se[c0+0] + sf[c0+0];
        o.y = lo.y + av2 * sc[c0+1] + av1 * se[c0+1] + sf[c0+1];
        o.z = hi.x + av2 * sc[c0+2] + av1 * se[c0+2] + sf[c0+2];
        o.w = hi.y + av2 * sc[c0+3] + av1 * se[c0+3] + sf[c0+3];
        *reinterpret_cast<float4*>(yrow + c0) = o;
    }
}

// ============================ launch ============================

extern "C" void kernel_launch(void* const* d_in, const int* in_sizes, int n_in,
                              void* d_out, int out_size) {
    const float* latent = (const float*)d_in[0];
    const float* cond   = (const float*)d_in[1];
    const int*   edge   = (const int*)  d_in[2];
    const float* W1 = (const float*)d_in[3];
    const float* b1 = (const float*)d_in[4];
    const float* W2 = (const float*)d_in[5];
    const float* b2 = (const float*)d_in[6];
    const float* W3 = (const float*)d_in[7];
    const float* b3 = (const float*)d_in[8];
    const float* W4 = (const float*)d_in[9];
    const float* b4 = (const float*)d_in[10];

    const int n = in_sizes[0] / 64;      // 100000
    const int E = in_sizes[2] / 2;       // 1600000
    const int* row = edge;
    const int* col = edge + E;

    static __half *pT0 = nullptr, *pT1 = nullptr, *pT2 = nullptr;
    static float *pY3 = nullptr;
    static cudaStream_t sB = nullptr;
    static cudaEvent_t ev0 = nullptr, evAdd = nullptr, evScale = nullptr,
                       evAgg1 = nullptr, evA2 = nullptr;
    if (!pT0) {
        cudaGetSymbolAddress((void**)&pT0,  g_T0);
        cudaGetSymbolAddress((void**)&pT1,  g_T1);
        cudaGetSymbolAddress((void**)&pT2,  g_T2);
        cudaGetSymbolAddress((void**)&pY3,  g_Y3);
        cudaStreamCreateWithFlags(&sB, cudaStreamNonBlocking);
        cudaEventCreateWithFlags(&ev0,     cudaEventDisableTiming);
        cudaEventCreateWithFlags(&evAdd,   cudaEventDisableTiming);
        cudaEventCreateWithFlags(&evScale, cudaEventDisableTiming);
        cudaEventCreateWithFlags(&evAgg1,  cudaEventDisableTiming);
        cudaEventCreateWithFlags(&evA2,    cudaEventDisableTiming);
    }

    const int TB  = 256;
    const int gN  = (n + TB - 1) / TB;
    const int gE  = (E + TB - 1) / TB;
    const int nbS = (n + 1023) / 1024;      // <= 98 <= 128
    const int gN1 = (n + 1 + TB - 1) / TB;
    const int gW  = (n + 7) / 8;            // warp per node, 8 warps/block
    const int gS  = (n * 8 + TB - 1) / TB;  // scale kernel

    // ---- fork: side stream B handles the weight path ----
    cudaEventRecord(ev0, 0);
    cudaStreamWaitEvent(sB, ev0, 0);
    k_wprep2<<<25, 256, 0, sB>>>(W1, W2, W3, W4, b1, b2, b3, b4);
    k_gemm0v<<<gN, TB, 0, sB>>>(latent, cond, n);   // V = [L|C]@U (unscaled)

    // ---- main stream: edge/build chain (no memset — cnt/a1f self-cleaned) ----
    k_hist<<<gE, TB>>>(col, E);
    k_scan_local<<<nbS, 1024>>>(n);
    k_scan_add<<<gN1, TB>>>(n, E, nbS);     // merged bsum-scan + finalize
    cudaEventRecord(evAdd, 0);
    k_fill<<<gE, TB>>>(row, col, E);

    // ---- side stream: scale T0 by dinv (needs scan_add + gemm0v), overlaps fill ----
    cudaStreamWaitEvent(sB, evAdd, 0);
    k_scale<<<gS, TB, 0, sB>>>(n);
    cudaEventRecord(evScale, sB);

    // ---- main stream: agg1 (finalizes a1/at), agg2, agg3 ----
    cudaStreamWaitEvent(0, evScale, 0);
    k_aggp<0, true ><<<gW, TB>>>(pT0, pT1, n);
    cudaEventRecord(evAgg1, 0);
    k_aggp<0, false><<<gW, TB>>>(pT1, pT2, n);
    k_aggp<1, false><<<gW, TB>>>(pT2, pY3, n);

    // ---- side stream: a2 gather (needs agg1's a1/at), overlaps agg2/agg3 ----
    cudaStreamWaitEvent(sB, evAgg1, 0);
    k_a2<<<gW, TB, 0, sB>>>(n);
    cudaEventRecord(evA2, sB);

    // ---- out = Y3@W4 + a2·c4 + a1·e4 + f4 ----
    cudaStreamWaitEvent(0, evA2, 0);
    k_gemm_final<<<gN, TB>>>(pY3, W4, (float*)d_out, n);
}